// round 15
// baseline (speedup 1.0000x reference)
#include <cuda_runtime.h>
#include <cuda_fp16.h>
#include <cstdint>

#define NB 1024
#define NT 240
#define NH 90
#define NF 180
#define KS 30

typedef unsigned long long ull;

// frag-image sizes (u32 words)
#define EB_G (12*32*28)  // enc gate image
#define DB_G (6*32*28)   // dec gate image

// lstm smem layout (bytes)
#define OFF_AH  0        // enc A fp16 [12kt][8mt][32][16B] = 49152
#define OFF_ADH 0        // dec A fp16 [6kt][8][32][16B] = 24576 (reuse)
#define OFF_B   49152    // 3 x 21504 chunk ring buffers (x staging 43200 overlaps)
#define CHUNK_B 21504
#define SMEM_LSTM (OFF_B + 3*CHUNK_B)   // 113664

// out_gemm smem (floats): Hs 240*67=16080 | Wt 240*44=10560
#define OG_HS_STRIDE 67
#define OG_SMEM_FLOATS (240*OG_HS_STRIDE + 240*44)

__device__ __align__(16) uint32_t g_eBF[3*EB_G];
__device__ __align__(16) uint32_t g_dBF[3*DB_G];
__device__ __half g_h2h[(size_t)NB*NT*NH];
__device__ float g_part[KS*NB*40];

// ---- helpers ----
static __device__ __forceinline__ uint32_t smem_u32(const void* p) {
    uint32_t a;
    asm("{ .reg .u64 t; cvta.to.shared.u64 t, %1; cvt.u32.u64 %0, t; }" : "=r"(a) : "l"(p));
    return a;
}
static __device__ __forceinline__ uint4 lds128(uint32_t a) {
    uint4 v;
    asm volatile("ld.shared.v4.b32 {%0,%1,%2,%3}, [%4];"
                 : "=r"(v.x), "=r"(v.y), "=r"(v.z), "=r"(v.w) : "r"(a));
    return v;
}
static __device__ __forceinline__ void sts32(uint32_t a, uint32_t v) {
    asm volatile("st.shared.b32 [%0], %1;" :: "r"(a), "r"(v));
}
static __device__ __forceinline__ void sts64(uint32_t a, uint32_t v0, uint32_t v1) {
    asm volatile("st.shared.v2.b32 [%0], {%1,%2};" :: "r"(a), "r"(v0), "r"(v1));
}
static __device__ __forceinline__ void sts128z(uint32_t a) {
    asm volatile("st.shared.v4.b32 [%0], {%1,%1,%1,%1};" :: "r"(a), "r"(0u));
}
static __device__ __forceinline__ void cp16(uint32_t saddr, const void* g) {
    asm volatile("{ .reg .u64 gp; cvta.to.global.u64 gp, %1;"
                 "  cp.async.cg.shared.global [%0], [gp], 16; }"
                 :: "r"(saddr), "l"(g) : "memory");
}
#define CP_COMMIT() asm volatile("cp.async.commit_group;" ::: "memory")
#define CP_WAIT1()  asm volatile("cp.async.wait_group 1;" ::: "memory")
#define CP_WAIT0()  asm volatile("cp.async.wait_group 0;" ::: "memory")

static __device__ __forceinline__ void mma4(float* c, const uint4& a, uint32_t b0, uint32_t b1) {
    asm volatile(
        "mma.sync.aligned.m16n8k16.row.col.f32.f16.f16.f32 "
        "{%0,%1,%2,%3}, {%4,%5,%6,%7}, {%8,%9}, {%0,%1,%2,%3};"
        : "+f"(c[0]), "+f"(c[1]), "+f"(c[2]), "+f"(c[3])
        : "r"(a.x), "r"(a.y), "r"(a.z), "r"(a.w), "r"(b0), "r"(b1));
}
static __device__ __forceinline__ float tanhA(float x) {
    float y;
    asm("tanh.approx.f32 %0, %1;" : "=f"(y) : "f"(x));
    return y;
}
static __device__ __forceinline__ float sigA(float x) {
    return fmaf(tanhA(0.5f * x), 0.5f, 0.5f);
}
static __device__ __forceinline__ uint32_t packh2(float v0, float v1) {
    __half2 h = __floats2half2_rn(v0, v1);
    return *reinterpret_cast<uint32_t*>(&h);
}
static __device__ __forceinline__ float2 unpkh2(uint32_t v) {
    __half2 h = *reinterpret_cast<__half2*>(&v);
    return __half22float2(h);
}
static __device__ __forceinline__ void ffma2(ull& c, ull a, ull b) {
    asm("fma.rn.f32x2 %0, %1, %2, %0;" : "+l"(c) : "l"(a), "l"(b));
}
static __device__ __forceinline__ ull pack2f(float x, float y) {
    ull r;
    asm("mov.b64 %0, {%1, %2};" : "=l"(r)
        : "r"(__float_as_uint(x)), "r"(__float_as_uint(y)));
    return r;
}
static __device__ __forceinline__ float2 unpk2f(ull v) {
    unsigned int lo, hi;
    asm("mov.b64 {%0, %1}, %2;" : "=r"(lo), "=r"(hi) : "l"(v));
    return make_float2(__uint_as_float(lo), __uint_as_float(hi));
}

#define MMA6(accp, A, B0, B1, B2) \
    mma4((accp) + 0,  A, B0.x, B0.y); mma4((accp) + 4,  A, B0.z, B0.w); \
    mma4((accp) + 8,  A, B1.x, B1.y); mma4((accp) + 12, A, B1.z, B1.w); \
    mma4((accp) + 16, A, B2.x, B2.y); mma4((accp) + 20, A, B2.z, B2.w);

// one 6-kt chunk with interleaved previous-gate epilogue (EPI 0=none 1=sig 2=cmul)
template <int EPI>
static __device__ __forceinline__ void chunk_mma(uint32_t abA, uint32_t bb,
                                                 uint32_t aoffb, uint32_t boffb,
                                                 float* acc, const float* old,
                                                 uint32_t* svp) {
#pragma unroll
    for (int kt = 0; kt < 6; ++kt) {
        uint32_t aa = abA + kt * 4096 + aoffb;
        uint4 a0 = lds128(aa), a1 = lds128(aa + 512);
        uint32_t bo = kt * 3584 + boffb;
        uint4 B0 = lds128(bb + bo), B1 = lds128(bb + bo + 16), B2 = lds128(bb + bo + 32);
        MMA6(acc,      a0, B0, B1, B2);
        MMA6(acc + 24, a1, B0, B1, B2);
        if (EPI == 1) {
#pragma unroll
            for (int u = 0; u < 2; ++u) {
                int g = 2 * kt + u;
                svp[2 * g]     = packh2(sigA(old[4 * g]),     sigA(old[4 * g + 1]));
                svp[2 * g + 1] = packh2(sigA(old[4 * g + 2]), sigA(old[4 * g + 3]));
            }
        } else if (EPI == 2) {
#pragma unroll
            for (int u = 0; u < 2; ++u) {
                int g = 2 * kt + u;
                float2 s0 = unpkh2(svp[2 * g]), s1 = unpkh2(svp[2 * g + 1]);
                svp[2 * g]     = packh2(s0.x * tanhA(old[4 * g]),
                                        s0.y * tanhA(old[4 * g + 1]));
                svp[2 * g + 1] = packh2(s1.x * tanhA(old[4 * g + 2]),
                                        s1.y * tanhA(old[4 * g + 3]));
            }
        }
    }
}

// ===== prep: pack fp16 weights (bias folded) into frag-major images =====
__global__ void prep_kernel(const float* __restrict__ eW, const float* __restrict__ eb1,
                            const float* __restrict__ eb2, const float* __restrict__ dW,
                            const float* __restrict__ db1, const float* __restrict__ db2) {
    int idx = blockIdx.x * 256 + threadIdx.x;
    const int goff[3] = {0, 180, 270};  // i, g, o (f gate skipped: c0 = 0)
    if (idx < 3 * 96 * 96) {
        int gate = idx / (96 * 96), rem = idx % (96 * 96);
        int n = rem / 96, kp = rem % 96;
        int k = 2 * kp;
        float v0 = 0.f, v1 = 0.f;
        if (n < NH) {
            if (k < NF) { v0 = eW[(goff[gate] + n) * NF + k]; v1 = eW[(goff[gate] + n) * NF + k + 1]; }
            else if (k == NF) v0 = eb1[goff[gate] + n] + eb2[goff[gate] + n];
        }
        int pos = ((kp >> 3) * 32 + ((n & 7) << 2) + (kp & 3)) * 28 + (n >> 3) * 2 + ((kp >> 2) & 1);
        g_eBF[gate * EB_G + pos] = packh2(v0, v1);
        return;
    }
    int j = idx - 3 * 96 * 96;
    if (j < 3 * 96 * 48) {
        int gate = j / (96 * 48), rem = j % (96 * 48);
        int n = rem / 48, kp = rem % 48;
        int k = 2 * kp;
        float v0 = 0.f, v1 = 0.f;
        if (n < NH) {
            if (k < NH) { v0 = dW[(goff[gate] + n) * NH + k]; v1 = dW[(goff[gate] + n) * NH + k + 1]; }
            else if (k == NH) v0 = db1[goff[gate] + n] + db2[goff[gate] + n];
        }
        int pos = ((kp >> 3) * 32 + ((n & 7) << 2) + (kp & 3)) * 28 + (n >> 3) * 2 + ((kp >> 2) & 1);
        g_dBF[gate * DB_G + pos] = packh2(v0, v1);
    }
}

// ===== fused LSTM: fp16 mma.sync, banked acc + pipelined epilogues, occ 1 =====
__global__ void __launch_bounds__(256, 1)
lstm_mma_kernel(const float* __restrict__ x) {
    extern __shared__ char smem[];
    const uint32_t sb = smem_u32(smem);
    const int tid = threadIdx.x, wid = tid >> 5, lane = tid & 31;
    const int b = blockIdx.x >> 1, th = blockIdx.x & 1;
    const int t0 = th * 120;
    const int tig = lane & 3, q = lane >> 2;
    const int mg = wid >> 1, ng = wid & 1;
    const uint32_t aoffb = (uint32_t)(mg * 2 * 512 + lane * 16);
    const uint32_t boffb = (uint32_t)(lane * 112 + ng * 48);

    // zero enc A region (49152B)
    for (int i = tid; i < 3072; i += 256) sts128z(sb + (uint32_t)(i * 16));

    // stage x coalesced, scatter fp16 into enc A frags (two 90-feature phases)
    float* Sx = reinterpret_cast<float*>(smem + OFF_B);
    for (int ph = 0; ph < 2; ++ph) {
        __syncthreads();
        const float* xb = x + ((size_t)b * NF + ph * 90) * NT + t0;
        for (int i = tid; i < 2700; i += 256) {
            int f = i / 30, c = i % 30;
            const float4 v = *reinterpret_cast<const float4*>(xb + f * NT + c * 4);
            *reinterpret_cast<float4*>(Sx + f * 120 + c * 4) = v;
        }
        __syncthreads();
        for (int i = tid; i < 5400; i += 256) {
            int r = i / 45, kpl = i % 45;
            int kp = ph * 45 + kpl, fp = 2 * kpl;
            uint32_t hv = packh2(Sx[fp * 120 + r], Sx[(fp + 1) * 120 + r]);
            int rr = r & 15, mt = r >> 4;
            int lne = ((rr & 7) << 2) | (kp & 3);
            int reg = (((kp >> 2) & 1) << 1) | (rr >> 3);
            uint32_t woff = (uint32_t)(((((kp >> 3) * 8 + mt) * 32 + lne) * 4 + reg) * 4);
            sts32(sb + OFF_AH + woff, hv);
        }
    }
    // enc bias column (k=180 -> kt 11, lane k-part 2, regs 0&1): fp16 1.0
    if (tid < 64) {
        int mt = tid >> 3, qq = tid & 7;
        uint32_t addr = sb + OFF_AH + (uint32_t)((((11 * 8 + mt) * 32 + ((qq << 2) | 2)) * 4) * 4);
        sts64(addr, 0x00003C00u, 0x00003C00u);
    }
    __syncthreads();  // Sx readers done before prefetch overwrites ring region

    auto src = [&](int c) -> const uint4* {
        if (c < 6) return reinterpret_cast<const uint4*>(g_eBF + (c >> 1) * EB_G + (c & 1) * 5376);
        return reinterpret_cast<const uint4*>(g_dBF + (c - 6) * DB_G);
    };
    auto prefetch = [&](int c) {
        uint32_t d = sb + OFF_B + (uint32_t)((c % 3) * CHUNK_B);
        const uint4* s = src(c);
        for (int i = tid; i < 1344; i += 256) cp16(d + (uint32_t)(i * 16), s + i);
        CP_COMMIT();
    };
    auto buf = [&](int c) -> uint32_t { return sb + OFF_B + (uint32_t)((c % 3) * CHUNK_B); };

    prefetch(0);
    prefetch(1);

    float accA[48], accB[48];
    uint32_t svp[24];

#define TOPC(c) do { if ((c) < 8) { CP_WAIT1(); } else { CP_WAIT0(); } \
                     __syncthreads(); if ((c) + 2 <= 8) prefetch((c) + 2); } while (0)
#define ZERO48(A) { _Pragma("unroll") for (int zi = 0; zi < 48; ++zi) (A)[zi] = 0.f; }

    const uint32_t encA0 = sb + OFF_AH, encA1 = sb + OFF_AH + 24576;
    const uint32_t decA = sb + OFF_ADH;

    // encoder gate i (bank A)
    TOPC(0); ZERO48(accA);
    chunk_mma<0>(encA0, buf(0), aoffb, boffb, accA, accB, svp);
    TOPC(1);
    chunk_mma<0>(encA1, buf(1), aoffb, boffb, accA, accB, svp);
    // encoder gate g (bank B), interleaved sig(i)
    TOPC(2); ZERO48(accB);
    chunk_mma<1>(encA0, buf(2), aoffb, boffb, accB, accA, svp);
    TOPC(3);
    chunk_mma<0>(encA1, buf(3), aoffb, boffb, accB, accA, svp);
    // encoder gate o (bank A), interleaved c = sig(i)*tanh(g)
    TOPC(4); ZERO48(accA);
    chunk_mma<2>(encA0, buf(4), aoffb, boffb, accA, accB, svp);
    TOPC(5);
    chunk_mma<0>(encA1, buf(5), aoffb, boffb, accA, accB, svp);

    // h1 = sig(sig(o)*tanh(c)) -> scatter fp16 into dec A frags (own-lane writes)
#pragma unroll
    for (int mi = 0; mi < 2; ++mi) {
#pragma unroll
        for (int ni = 0; ni < 6; ++ni) {
            int g = mi * 6 + ni;
            const float* a = accA + g * 4;
            int nt = ng * 6 + ni;
            uint32_t hv1, hv2;
            if (nt == 11 && tig >= 1) {
                hv1 = hv2 = (tig == 1) ? 0x00003C00u : 0u;  // dec bias col j=90
            } else {
                float2 c0 = unpkh2(svp[2 * g]), c1 = unpkh2(svp[2 * g + 1]);
                hv1 = packh2(sigA(sigA(a[0]) * tanhA(c0.x)),
                             sigA(sigA(a[1]) * tanhA(c0.y)));
                hv2 = packh2(sigA(sigA(a[2]) * tanhA(c1.x)),
                             sigA(sigA(a[3]) * tanhA(c1.y)));
            }
            int jp = nt * 4 + tig;
            int ktd = jp >> 3, regb = ((jp >> 2) & 1) << 1;
            int mtd = mg * 2 + mi;
            uint32_t w = decA + (uint32_t)(((((ktd * 8 + mtd) * 32 + lane) * 4) + regb) * 4);
            sts64(w, hv1, hv2);
        }
    }

    // decoder gate i (bank A)  — TOPC(6) barrier publishes the dec-A scatter
    TOPC(6); ZERO48(accA);
    chunk_mma<0>(decA, buf(6), aoffb, boffb, accA, accB, svp);
    // decoder gate g (bank B), interleaved sig(dec_i)
    TOPC(7); ZERO48(accB);
    chunk_mma<1>(decA, buf(7), aoffb, boffb, accB, accA, svp);
    // decoder gate o (bank A), interleaved c = sig(i)*tanh(g)
    TOPC(8); ZERO48(accA);
    chunk_mma<2>(decA, buf(8), aoffb, boffb, accA, accB, svp);

    // h2 = sig(o)*tanh(c) -> g_h2h (fp16)
    {
        __half* hb = g_h2h + (size_t)b * (NT * NH) + (size_t)t0 * NH;
#pragma unroll
        for (int mi = 0; mi < 2; ++mi) {
#pragma unroll
            for (int ni = 0; ni < 6; ++ni) {
                int nt = ng * 6 + ni;
                if (nt == 11 && tig >= 1) continue;
                int g = mi * 6 + ni;
                const float* a = accA + g * 4;
                float2 c0 = unpkh2(svp[2 * g]), c1 = unpkh2(svp[2 * g + 1]);
                int j0 = nt * 8 + 2 * tig;
                int r1 = (mg * 2 + mi) * 16 + q, r2 = r1 + 8;
                uint32_t p1 = packh2(sigA(a[0]) * tanhA(c0.x),
                                     sigA(a[1]) * tanhA(c0.y));
                *reinterpret_cast<uint32_t*>(hb + r1 * NH + j0) = p1;
                if (r2 < 120) {
                    uint32_t p2 = packh2(sigA(a[2]) * tanhA(c1.x),
                                         sigA(a[3]) * tanhA(c1.y));
                    *reinterpret_cast<uint32_t*>(hb + r2 * NH + j0) = p2;
                }
            }
        }
    }
#undef TOPC
#undef ZERO48
}

// ===== output GEMM: 512 threads, 64 batches/block (halved W traffic) =====
__global__ void __launch_bounds__(512, 1)
out_gemm_kernel(const float* __restrict__ W) {
    extern __shared__ float sm[];
    float* Hs = sm;                          // [240][67]
    float* Wt = sm + 240 * OG_HS_STRIDE;     // [240][44]
    const int b0 = blockIdx.y * 64;
    const int k0 = blockIdx.x * (21600 / KS);
    const int tid = threadIdx.x, wi = tid >> 5, lane = tid & 31;
    const int bbl = (wi & 1) * 32 + lane;    // local batch column 0..63
    const int ksl = wi >> 1;                 // k-slice 0..7

    ull acc[20];
#pragma unroll
    for (int n = 0; n < 20; ++n) acc[n] = 0ull;

    for (int tile = 0; tile < (21600 / KS) / 240; ++tile) {
        const int kt = k0 + tile * 240;
        __syncthreads();
        for (int idx = tid; idx < 64 * 120; idx += 512) {
            int bb = idx / 120, k2 = idx - bb * 120;
            __half2 h = *reinterpret_cast<const __half2*>(
                g_h2h + (size_t)(b0 + bb) * 21600 + kt + 2 * k2);
            float2 f = __half22float2(h);
            Hs[(2 * k2) * OG_HS_STRIDE + bb] = f.x;
            Hs[(2 * k2 + 1) * OG_HS_STRIDE + bb] = f.y;
        }
        for (int idx = tid; idx < 40 * 240; idx += 512) {
            int n = idx / 240, k = idx - n * 240;
            Wt[k * 44 + n] = W[(size_t)n * 21600 + kt + k];
        }
        __syncthreads();
#pragma unroll 2
        for (int kk = 0; kk < 30; ++kk) {
            int k = ksl * 30 + kk;
            float h = Hs[k * OG_HS_STRIDE + bbl];
            ull hh = pack2f(h, h);
            const ull* wp = reinterpret_cast<const ull*>(Wt + k * 44);
#pragma unroll
            for (int n2 = 0; n2 < 20; ++n2) ffma2(acc[n2], hh, wp[n2]);
        }
    }
    __syncthreads();
    float* Rs = sm;   // [8 ksl][64 bb][40] = 20480 floats
#pragma unroll
    for (int n2 = 0; n2 < 20; ++n2) {
        float2 v = unpk2f(acc[n2]);
        Rs[(ksl * 64 + bbl) * 40 + 2 * n2] = v.x;
        Rs[(ksl * 64 + bbl) * 40 + 2 * n2 + 1] = v.y;
    }
    __syncthreads();
    for (int idx = tid; idx < 64 * 40; idx += 512) {
        int bb = idx / 40, n = idx - bb * 40;
        float s = 0.f;
#pragma unroll
        for (int w = 0; w < 8; ++w) s += Rs[(w * 64 + bb) * 40 + n];
        g_part[blockIdx.x * (NB * 40) + (b0 + bb) * 40 + n] = s;
    }
}

// 4 batches per 160-thread block
__global__ void softmax_kernel(const float* __restrict__ ob, float* __restrict__ out) {
    __shared__ float L[160];
    __shared__ float E[160];
    const int tl = threadIdx.x;
    const int bl = tl / 40, n = tl - bl * 40;
    const int b = blockIdx.x * 4 + bl;
    float s = 0.f;
#pragma unroll
    for (int ks = 0; ks < KS; ++ks) s += g_part[ks * (NB * 40) + b * 40 + n];
    s += ob[n];
    L[tl] = s;
    __syncthreads();
    const int g0 = bl * 40 + (n / 10) * 10;
    float mx = -1e30f;
#pragma unroll
    for (int i = 0; i < 10; ++i) mx = fmaxf(mx, L[g0 + i]);
    float e = __expf(s - mx);
    E[tl] = e;
    __syncthreads();
    float sum = 0.f;
#pragma unroll
    for (int i = 0; i < 10; ++i) sum += E[g0 + i];
    out[b * 40 + n] = __fdividef(e, sum);
}

extern "C" void kernel_launch(void* const* d_in, const int* in_sizes, int n_in,
                              void* d_out, int out_size) {
    const float* x   = (const float*)d_in[0];
    const float* eW  = (const float*)d_in[1];
    const float* eb1 = (const float*)d_in[2];
    const float* eb2 = (const float*)d_in[3];
    const float* dW  = (const float*)d_in[4];
    const float* db1 = (const float*)d_in[5];
    const float* db2 = (const float*)d_in[6];
    const float* oW  = (const float*)d_in[7];
    const float* ob  = (const float*)d_in[8];
    float* out = (float*)d_out;

    cudaFuncSetAttribute(lstm_mma_kernel,
                         cudaFuncAttributeMaxDynamicSharedMemorySize, SMEM_LSTM);
    cudaFuncSetAttribute(out_gemm_kernel,
                         cudaFuncAttributeMaxDynamicSharedMemorySize,
                         OG_SMEM_FLOATS * 4);

    prep_kernel<<<162, 256>>>(eW, eb1, eb2, dW, db1, db2);
    lstm_mma_kernel<<<2048, 256, SMEM_LSTM>>>(x);
    out_gemm_kernel<<<dim3(KS, 16), 512, OG_SMEM_FLOATS * 4>>>(oW);
    softmax_kernel<<<256, 160>>>(ob, out);
}

// round 16
// speedup vs baseline: 1.2219x; 1.2219x over previous
#include <cuda_runtime.h>
#include <cuda_fp16.h>
#include <cstdint>

#define NB 1024
#define NT 240
#define NH 90
#define NF 180
#define KS 30

typedef unsigned long long ull;

// frag-image sizes (u32 words)
#define EB_G (12*32*28)  // enc gate image
#define DB_G (6*32*28)   // dec gate image

// lstm smem layout (bytes)
#define OFF_AH  0        // enc A fp16 [12kt][8mt][32][16B] = 49152
#define OFF_ADH 0        // dec A fp16 [6kt][8][32][16B] = 24576 (reuse)
#define OFF_B   49152    // 2 x 21504 chunk buffers
#define CHUNK_B 21504
#define SMEM_LSTM (OFF_B + 43200)   // 92352: x staging needs 43200B

// out_gemm smem (floats): Hs [240][131] = 31440 | Wt [240][44] = 10560
#define OG_HS_STRIDE 131
#define OG_SMEM_FLOATS (240*OG_HS_STRIDE + 240*44)

__device__ __align__(16) uint32_t g_eBF[3*EB_G];
__device__ __align__(16) uint32_t g_dBF[3*DB_G];
__device__ __half g_h2h[(size_t)NB*NT*NH];
__device__ float g_part[KS*NB*40];

// ---- helpers ----
static __device__ __forceinline__ uint32_t smem_u32(const void* p) {
    uint32_t a;
    asm("{ .reg .u64 t; cvta.to.shared.u64 t, %1; cvt.u32.u64 %0, t; }" : "=r"(a) : "l"(p));
    return a;
}
static __device__ __forceinline__ uint4 lds128(uint32_t a) {
    uint4 v;
    asm volatile("ld.shared.v4.b32 {%0,%1,%2,%3}, [%4];"
                 : "=r"(v.x), "=r"(v.y), "=r"(v.z), "=r"(v.w) : "r"(a));
    return v;
}
static __device__ __forceinline__ void sts32(uint32_t a, uint32_t v) {
    asm volatile("st.shared.b32 [%0], %1;" :: "r"(a), "r"(v));
}
static __device__ __forceinline__ void sts64(uint32_t a, uint32_t v0, uint32_t v1) {
    asm volatile("st.shared.v2.b32 [%0], {%1,%2};" :: "r"(a), "r"(v0), "r"(v1));
}
static __device__ __forceinline__ void sts128z(uint32_t a) {
    asm volatile("st.shared.v4.b32 [%0], {%1,%1,%1,%1};" :: "r"(a), "r"(0u));
}
static __device__ __forceinline__ void cp16(uint32_t saddr, const void* g) {
    asm volatile("{ .reg .u64 gp; cvta.to.global.u64 gp, %1;"
                 "  cp.async.cg.shared.global [%0], [gp], 16; }"
                 :: "r"(saddr), "l"(g) : "memory");
}
#define CP_COMMIT() asm volatile("cp.async.commit_group;" ::: "memory")
#define CP_WAIT1()  asm volatile("cp.async.wait_group 1;" ::: "memory")
#define CP_WAIT0()  asm volatile("cp.async.wait_group 0;" ::: "memory")

static __device__ __forceinline__ void mma4(float* c, const uint4& a, uint32_t b0, uint32_t b1) {
    asm volatile(
        "mma.sync.aligned.m16n8k16.row.col.f32.f16.f16.f32 "
        "{%0,%1,%2,%3}, {%4,%5,%6,%7}, {%8,%9}, {%0,%1,%2,%3};"
        : "+f"(c[0]), "+f"(c[1]), "+f"(c[2]), "+f"(c[3])
        : "r"(a.x), "r"(a.y), "r"(a.z), "r"(a.w), "r"(b0), "r"(b1));
}
static __device__ __forceinline__ float tanhA(float x) {
    float y;
    asm("tanh.approx.f32 %0, %1;" : "=f"(y) : "f"(x));
    return y;
}
static __device__ __forceinline__ float sigA(float x) {
    return fmaf(tanhA(0.5f * x), 0.5f, 0.5f);
}
static __device__ __forceinline__ uint32_t packh2(float v0, float v1) {
    __half2 h = __floats2half2_rn(v0, v1);
    return *reinterpret_cast<uint32_t*>(&h);
}
static __device__ __forceinline__ float2 unpkh2(uint32_t v) {
    __half2 h = *reinterpret_cast<__half2*>(&v);
    return __half22float2(h);
}
static __device__ __forceinline__ void ffma2(ull& c, ull a, ull b) {
    asm("fma.rn.f32x2 %0, %1, %2, %0;" : "+l"(c) : "l"(a), "l"(b));
}
static __device__ __forceinline__ ull pack2f(float x, float y) {
    ull r;
    asm("mov.b64 %0, {%1, %2};" : "=l"(r)
        : "r"(__float_as_uint(x)), "r"(__float_as_uint(y)));
    return r;
}
static __device__ __forceinline__ float2 unpk2f(ull v) {
    unsigned int lo, hi;
    asm("mov.b64 {%0, %1}, %2;" : "=r"(lo), "=r"(hi) : "l"(v));
    return make_float2(__uint_as_float(lo), __uint_as_float(hi));
}

#define MMA6(accp, A, B0, B1, B2) \
    mma4((accp) + 0,  A, B0.x, B0.y); mma4((accp) + 4,  A, B0.z, B0.w); \
    mma4((accp) + 8,  A, B1.x, B1.y); mma4((accp) + 12, A, B1.z, B1.w); \
    mma4((accp) + 16, A, B2.x, B2.y); mma4((accp) + 20, A, B2.z, B2.w);

// one 6-kt chunk, single fp16 pass; warp covers 2 mtiles x 6 ntiles
static __device__ __forceinline__ void chunk_mma(uint32_t abA, uint32_t bb,
                                                 uint32_t aoffb, uint32_t boffb, float* acc) {
#pragma unroll
    for (int kt = 0; kt < 6; ++kt) {
        uint32_t aa = abA + kt * 4096 + aoffb;
        uint4 a0 = lds128(aa), a1 = lds128(aa + 512);
        uint32_t bo = kt * 3584 + boffb;
        uint4 B0 = lds128(bb + bo), B1 = lds128(bb + bo + 16), B2 = lds128(bb + bo + 32);
        MMA6(acc,      a0, B0, B1, B2);
        MMA6(acc + 24, a1, B0, B1, B2);
    }
}

// ===== prep: pack fp16 weights (bias folded) into frag-major images =====
__global__ void prep_kernel(const float* __restrict__ eW, const float* __restrict__ eb1,
                            const float* __restrict__ eb2, const float* __restrict__ dW,
                            const float* __restrict__ db1, const float* __restrict__ db2) {
    int idx = blockIdx.x * 256 + threadIdx.x;
    const int goff[3] = {0, 180, 270};  // i, g, o (f gate skipped: c0 = 0)
    if (idx < 3 * 96 * 96) {
        int gate = idx / (96 * 96), rem = idx % (96 * 96);
        int n = rem / 96, kp = rem % 96;
        int k = 2 * kp;
        float v0 = 0.f, v1 = 0.f;
        if (n < NH) {
            if (k < NF) { v0 = eW[(goff[gate] + n) * NF + k]; v1 = eW[(goff[gate] + n) * NF + k + 1]; }
            else if (k == NF) v0 = eb1[goff[gate] + n] + eb2[goff[gate] + n];
        }
        int pos = ((kp >> 3) * 32 + ((n & 7) << 2) + (kp & 3)) * 28 + (n >> 3) * 2 + ((kp >> 2) & 1);
        g_eBF[gate * EB_G + pos] = packh2(v0, v1);
        return;
    }
    int j = idx - 3 * 96 * 96;
    if (j < 3 * 96 * 48) {
        int gate = j / (96 * 48), rem = j % (96 * 48);
        int n = rem / 48, kp = rem % 48;
        int k = 2 * kp;
        float v0 = 0.f, v1 = 0.f;
        if (n < NH) {
            if (k < NH) { v0 = dW[(goff[gate] + n) * NH + k]; v1 = dW[(goff[gate] + n) * NH + k + 1]; }
            else if (k == NH) v0 = db1[goff[gate] + n] + db2[goff[gate] + n];
        }
        int pos = ((kp >> 3) * 32 + ((n & 7) << 2) + (kp & 3)) * 28 + (n >> 3) * 2 + ((kp >> 2) & 1);
        g_dBF[gate * DB_G + pos] = packh2(v0, v1);
    }
}

// ===== fused LSTM: single-pass fp16 mma.sync, 2 CTAs/SM (R10/R14 shape) =====
__global__ void __launch_bounds__(256, 2)
lstm_mma_kernel(const float* __restrict__ x) {
    extern __shared__ char smem[];
    const uint32_t sb = smem_u32(smem);
    const int tid = threadIdx.x, wid = tid >> 5, lane = tid & 31;
    const int b = blockIdx.x >> 1, th = blockIdx.x & 1;
    const int t0 = th * 120;
    const int tig = lane & 3, q = lane >> 2;
    const int mg = wid >> 1, ng = wid & 1;
    const uint32_t aoffb = (uint32_t)(mg * 2 * 512 + lane * 16);
    const uint32_t boffb = (uint32_t)(lane * 112 + ng * 48);

    // zero enc A region (49152B)
    for (int i = tid; i < 3072; i += 256) sts128z(sb + (uint32_t)(i * 16));

    // stage x coalesced, scatter fp16 into enc A frags (two 90-feature phases)
    float* Sx = reinterpret_cast<float*>(smem + OFF_B);
    for (int ph = 0; ph < 2; ++ph) {
        __syncthreads();
        const float* xb = x + ((size_t)b * NF + ph * 90) * NT + t0;
        for (int i = tid; i < 2700; i += 256) {
            int f = i / 30, c = i % 30;
            const float4 v = *reinterpret_cast<const float4*>(xb + f * NT + c * 4);
            *reinterpret_cast<float4*>(Sx + f * 120 + c * 4) = v;
        }
        __syncthreads();
        for (int i = tid; i < 5400; i += 256) {
            int r = i / 45, kpl = i % 45;
            int kp = ph * 45 + kpl, fp = 2 * kpl;
            uint32_t hv = packh2(Sx[fp * 120 + r], Sx[(fp + 1) * 120 + r]);
            int rr = r & 15, mt = r >> 4;
            int lne = ((rr & 7) << 2) | (kp & 3);
            int reg = (((kp >> 2) & 1) << 1) | (rr >> 3);
            uint32_t woff = (uint32_t)(((((kp >> 3) * 8 + mt) * 32 + lne) * 4 + reg) * 4);
            sts32(sb + OFF_AH + woff, hv);
        }
    }
    // enc bias column (k=180 -> kt 11, lane k-part 2, regs 0&1): fp16 1.0
    if (tid < 64) {
        int mt = tid >> 3, qq = tid & 7;
        uint32_t addr = sb + OFF_AH + (uint32_t)((((11 * 8 + mt) * 32 + ((qq << 2) | 2)) * 4) * 4);
        sts64(addr, 0x00003C00u, 0x00003C00u);
    }
    __syncthreads();  // Sx readers done before prefetch overwrites B region

    auto src = [&](int c) -> const uint4* {
        if (c < 6) return reinterpret_cast<const uint4*>(g_eBF + (c >> 1) * EB_G + (c & 1) * 5376);
        return reinterpret_cast<const uint4*>(g_dBF + (c - 6) * DB_G);
    };
    auto prefetch = [&](int c) {
        uint32_t d = sb + OFF_B + (uint32_t)((c & 1) * CHUNK_B);
        const uint4* s = src(c);
        for (int i = tid; i < 1344; i += 256) cp16(d + (uint32_t)(i * 16), s + i);
        CP_COMMIT();
    };

    prefetch(0);
    prefetch(1);

    float acc[48];
    uint32_t svp[24];   // packed fp16 gate-state carry (sig(i), then c)

#pragma unroll
    for (int c = 0; c < 9; ++c) {
        if (c < 8) { CP_WAIT1(); } else { CP_WAIT0(); }
        __syncthreads();  // chunk c visible; prior epilogue smem writes visible

        if (c == 0 || c == 2 || c == 4 || c >= 6) {
#pragma unroll
            for (int i = 0; i < 48; ++i) acc[i] = 0.f;
        }
        uint32_t abA = (c < 6) ? (sb + OFF_AH + (uint32_t)((c & 1) * 24576))
                               : (sb + OFF_ADH);
        uint32_t bb = sb + OFF_B + (uint32_t)((c & 1) * CHUNK_B);
        chunk_mma(abA, bb, aoffb, boffb, acc);

        if (c == 5) __syncthreads();  // all enc-A readers done before dec-A scatter

        // epilogues
        if (c == 1 || c == 6) {
#pragma unroll
            for (int g = 0; g < 12; ++g) {
                svp[2 * g]     = packh2(sigA(acc[4 * g]),     sigA(acc[4 * g + 1]));
                svp[2 * g + 1] = packh2(sigA(acc[4 * g + 2]), sigA(acc[4 * g + 3]));
            }
        } else if (c == 3 || c == 7) {
#pragma unroll
            for (int g = 0; g < 12; ++g) {
                float2 s0 = unpkh2(svp[2 * g]), s1 = unpkh2(svp[2 * g + 1]);
                svp[2 * g]     = packh2(s0.x * tanhA(acc[4 * g]),
                                        s0.y * tanhA(acc[4 * g + 1]));
                svp[2 * g + 1] = packh2(s1.x * tanhA(acc[4 * g + 2]),
                                        s1.y * tanhA(acc[4 * g + 3]));
            }
        } else if (c == 5) {
            // h1 = sig(sig(o)*tanh(c)) -> scatter fp16 into dec A frags (own-lane writes)
#pragma unroll
            for (int mi = 0; mi < 2; ++mi) {
#pragma unroll
                for (int ni = 0; ni < 6; ++ni) {
                    int g = mi * 6 + ni;
                    const float* a = acc + g * 4;
                    int nt = ng * 6 + ni;
                    uint32_t hv1, hv2;
                    if (nt == 11 && tig >= 1) {
                        hv1 = hv2 = (tig == 1) ? 0x00003C00u : 0u;  // dec bias col j=90
                    } else {
                        float2 c0 = unpkh2(svp[2 * g]), c1 = unpkh2(svp[2 * g + 1]);
                        hv1 = packh2(sigA(sigA(a[0]) * tanhA(c0.x)),
                                     sigA(sigA(a[1]) * tanhA(c0.y)));
                        hv2 = packh2(sigA(sigA(a[2]) * tanhA(c1.x)),
                                     sigA(sigA(a[3]) * tanhA(c1.y)));
                    }
                    int jp = nt * 4 + tig;
                    int ktd = jp >> 3, regb = ((jp >> 2) & 1) << 1;
                    int mtd = mg * 2 + mi;
                    uint32_t w = sb + OFF_ADH +
                        (uint32_t)(((((ktd * 8 + mtd) * 32 + lane) * 4) + regb) * 4);
                    sts64(w, hv1, hv2);
                }
            }
        } else if (c == 8) {
            // h2 = sig(o)*tanh(c) -> g_h2h (fp16)
            __half* hb = g_h2h + (size_t)b * (NT * NH) + (size_t)t0 * NH;
#pragma unroll
            for (int mi = 0; mi < 2; ++mi) {
#pragma unroll
                for (int ni = 0; ni < 6; ++ni) {
                    int nt = ng * 6 + ni;
                    if (nt == 11 && tig >= 1) continue;
                    int g = mi * 6 + ni;
                    const float* a = acc + g * 4;
                    float2 c0 = unpkh2(svp[2 * g]), c1 = unpkh2(svp[2 * g + 1]);
                    int j0 = nt * 8 + 2 * tig;
                    int r1 = (mg * 2 + mi) * 16 + q, r2 = r1 + 8;
                    uint32_t p1 = packh2(sigA(a[0]) * tanhA(c0.x),
                                         sigA(a[1]) * tanhA(c0.y));
                    *reinterpret_cast<uint32_t*>(hb + r1 * NH + j0) = p1;
                    if (r2 < 120) {
                        uint32_t p2 = packh2(sigA(a[2]) * tanhA(c1.x),
                                             sigA(a[3]) * tanhA(c1.y));
                        *reinterpret_cast<uint32_t*>(hb + r2 * NH + j0) = p2;
                    }
                }
            }
        }

        __syncthreads();  // buf[c&1] readers done; epilogue smem writes published
        if (c + 2 < 9) prefetch(c + 2);
    }
}

// ===== output GEMM: 512 threads, 128 batches/block (quartered W traffic) =====
__global__ void __launch_bounds__(512, 1)
out_gemm_kernel(const float* __restrict__ W) {
    extern __shared__ float sm[];
    float* Hs = sm;                          // [240][131]
    float* Wt = sm + 240 * OG_HS_STRIDE;     // [240][44]
    const int b0 = blockIdx.y * 128;
    const int k0 = blockIdx.x * (21600 / KS);
    const int tid = threadIdx.x, wi = tid >> 5, lane = tid & 31;
    const int bbl = (wi & 3) * 32 + lane;    // local batch column 0..127
    const int ksl = wi >> 2;                 // k-slice 0..3 (60 k each)

    ull acc[20];
#pragma unroll
    for (int n = 0; n < 20; ++n) acc[n] = 0ull;

    for (int tile = 0; tile < (21600 / KS) / 240; ++tile) {
        const int kt = k0 + tile * 240;
        __syncthreads();
        for (int idx = tid; idx < 128 * 120; idx += 512) {
            int bb = idx / 120, k2 = idx - bb * 120;
            __half2 h = *reinterpret_cast<const __half2*>(
                g_h2h + (size_t)(b0 + bb) * 21600 + kt + 2 * k2);
            float2 f = __half22float2(h);
            Hs[(2 * k2) * OG_HS_STRIDE + bb] = f.x;
            Hs[(2 * k2 + 1) * OG_HS_STRIDE + bb] = f.y;
        }
        for (int idx = tid; idx < 40 * 240; idx += 512) {
            int n = idx / 240, k = idx - n * 240;
            Wt[k * 44 + n] = W[(size_t)n * 21600 + kt + k];
        }
        __syncthreads();
#pragma unroll 2
        for (int kk = 0; kk < 60; ++kk) {
            int k = ksl * 60 + kk;
            float h = Hs[k * OG_HS_STRIDE + bbl];
            ull hh = pack2f(h, h);
            const ull* wp = reinterpret_cast<const ull*>(Wt + k * 44);
#pragma unroll
            for (int n2 = 0; n2 < 20; ++n2) ffma2(acc[n2], hh, wp[n2]);
        }
    }
    __syncthreads();
    float* Rs = sm;   // [4 ksl][128 bb][40] = 20480 floats (fits)
#pragma unroll
    for (int n2 = 0; n2 < 20; ++n2) {
        float2 v = unpk2f(acc[n2]);
        Rs[(ksl * 128 + bbl) * 40 + 2 * n2] = v.x;
        Rs[(ksl * 128 + bbl) * 40 + 2 * n2 + 1] = v.y;
    }
    __syncthreads();
    for (int idx = tid; idx < 128 * 40; idx += 512) {
        int bb = idx / 40, n = idx - bb * 40;
        float s = 0.f;
#pragma unroll
        for (int w = 0; w < 4; ++w) s += Rs[(w * 128 + bb) * 40 + n];
        g_part[blockIdx.x * (NB * 40) + (b0 + bb) * 40 + n] = s;
    }
}

// 4 batches per 160-thread block
__global__ void softmax_kernel(const float* __restrict__ ob, float* __restrict__ out) {
    __shared__ float L[160];
    __shared__ float E[160];
    const int tl = threadIdx.x;
    const int bl = tl / 40, n = tl - bl * 40;
    const int b = blockIdx.x * 4 + bl;
    float s = 0.f;
#pragma unroll
    for (int ks = 0; ks < KS; ++ks) s += g_part[ks * (NB * 40) + b * 40 + n];
    s += ob[n];
    L[tl] = s;
    __syncthreads();
    const int g0 = bl * 40 + (n / 10) * 10;
    float mx = -1e30f;
#pragma unroll
    for (int i = 0; i < 10; ++i) mx = fmaxf(mx, L[g0 + i]);
    float e = __expf(s - mx);
    E[tl] = e;
    __syncthreads();
    float sum = 0.f;
#pragma unroll
    for (int i = 0; i < 10; ++i) sum += E[g0 + i];
    out[b * 40 + n] = __fdividef(e, sum);
}

extern "C" void kernel_launch(void* const* d_in, const int* in_sizes, int n_in,
                              void* d_out, int out_size) {
    const float* x   = (const float*)d_in[0];
    const float* eW  = (const float*)d_in[1];
    const float* eb1 = (const float*)d_in[2];
    const float* eb2 = (const float*)d_in[3];
    const float* dW  = (const float*)d_in[4];
    const float* db1 = (const float*)d_in[5];
    const float* db2 = (const float*)d_in[6];
    const float* oW  = (const float*)d_in[7];
    const float* ob  = (const float*)d_in[8];
    float* out = (float*)d_out;

    cudaFuncSetAttribute(lstm_mma_kernel,
                         cudaFuncAttributeMaxDynamicSharedMemorySize, SMEM_LSTM);
    cudaFuncSetAttribute(out_gemm_kernel,
                         cudaFuncAttributeMaxDynamicSharedMemorySize,
                         OG_SMEM_FLOATS * 4);

    prep_kernel<<<162, 256>>>(eW, eb1, eb2, dW, db1, db2);
    lstm_mma_kernel<<<2048, 256, SMEM_LSTM>>>(x);
    out_gemm_kernel<<<dim3(KS, 8), 512, OG_SMEM_FLOATS * 4>>>(oW);
    softmax_kernel<<<256, 160>>>(ob, out);
}

// round 17
// speedup vs baseline: 1.2270x; 1.0042x over previous
#include <cuda_runtime.h>
#include <cuda_fp16.h>
#include <cstdint>

#define NB 1024
#define NT 240
#define NH 90
#define NF 180
#define KS 30

typedef unsigned long long ull;

// frag-image sizes (u32 words)
#define EB_G (12*32*28)  // enc gate image
#define DB_G (6*32*28)   // dec gate image

// lstm smem layout (bytes)
#define OFF_AH  0        // enc A fp16 [12kt][8mt][32][16B] = 49152
#define OFF_ADH 0        // dec A fp16 [6kt][8][32][16B] = 24576 (reuse)
#define OFF_B   49152    // 2 x 21504 chunk buffers
#define CHUNK_B 21504
#define SMEM_LSTM (OFF_B + 43200)   // 92352: x staging needs 43200B

// out_gemm smem (floats): Hs [240][131] = 31440 | Wt [240][44] = 10560
#define OG_HS_STRIDE 131
#define OG_SMEM_FLOATS (240*OG_HS_STRIDE + 240*44)

__device__ __align__(16) uint32_t g_eBF[3*EB_G];
__device__ __align__(16) uint32_t g_dBF[3*DB_G];
__device__ __half g_h2h[(size_t)NB*NT*NH];
__device__ float g_part[KS*NB*40];

// ---- helpers ----
static __device__ __forceinline__ uint32_t smem_u32(const void* p) {
    uint32_t a;
    asm("{ .reg .u64 t; cvta.to.shared.u64 t, %1; cvt.u32.u64 %0, t; }" : "=r"(a) : "l"(p));
    return a;
}
static __device__ __forceinline__ uint4 lds128(uint32_t a) {
    uint4 v;
    asm volatile("ld.shared.v4.b32 {%0,%1,%2,%3}, [%4];"
                 : "=r"(v.x), "=r"(v.y), "=r"(v.z), "=r"(v.w) : "r"(a));
    return v;
}
static __device__ __forceinline__ void sts32(uint32_t a, uint32_t v) {
    asm volatile("st.shared.b32 [%0], %1;" :: "r"(a), "r"(v));
}
static __device__ __forceinline__ void sts64(uint32_t a, uint32_t v0, uint32_t v1) {
    asm volatile("st.shared.v2.b32 [%0], {%1,%2};" :: "r"(a), "r"(v0), "r"(v1));
}
static __device__ __forceinline__ void sts128z(uint32_t a) {
    asm volatile("st.shared.v4.b32 [%0], {%1,%1,%1,%1};" :: "r"(a), "r"(0u));
}
static __device__ __forceinline__ void cp16(uint32_t saddr, const void* g) {
    asm volatile("{ .reg .u64 gp; cvta.to.global.u64 gp, %1;"
                 "  cp.async.cg.shared.global [%0], [gp], 16; }"
                 :: "r"(saddr), "l"(g) : "memory");
}
#define CP_COMMIT() asm volatile("cp.async.commit_group;" ::: "memory")
#define CP_WAIT1()  asm volatile("cp.async.wait_group 1;" ::: "memory")
#define CP_WAIT0()  asm volatile("cp.async.wait_group 0;" ::: "memory")

static __device__ __forceinline__ void mma4(float* c, const uint4& a, uint32_t b0, uint32_t b1) {
    asm volatile(
        "mma.sync.aligned.m16n8k16.row.col.f32.f16.f16.f32 "
        "{%0,%1,%2,%3}, {%4,%5,%6,%7}, {%8,%9}, {%0,%1,%2,%3};"
        : "+f"(c[0]), "+f"(c[1]), "+f"(c[2]), "+f"(c[3])
        : "r"(a.x), "r"(a.y), "r"(a.z), "r"(a.w), "r"(b0), "r"(b1));
}
static __device__ __forceinline__ float tanhA(float x) {
    float y;
    asm("tanh.approx.f32 %0, %1;" : "=f"(y) : "f"(x));
    return y;
}
static __device__ __forceinline__ uint32_t packh2(float v0, float v1) {
    __half2 h = __floats2half2_rn(v0, v1);
    return *reinterpret_cast<uint32_t*>(&h);
}
static __device__ __forceinline__ __half2 u2h(uint32_t v) {
    return *reinterpret_cast<__half2*>(&v);
}
static __device__ __forceinline__ uint32_t h2u(__half2 h) {
    return *reinterpret_cast<uint32_t*>(&h);
}
// packed tanh: two tanh in one MUFU op
static __device__ __forceinline__ uint32_t h2tanh(uint32_t x) {
    uint32_t y;
    asm("tanh.approx.f16x2 %0, %1;" : "=r"(y) : "r"(x));
    return y;
}
// packed sigmoid: sig(x) = 0.5*tanh(0.5x) + 0.5
static __device__ __forceinline__ uint32_t h2sig(uint32_t x) {
    const __half2 half05 = __float2half2_rn(0.5f);
    __half2 t = u2h(h2tanh(h2u(__hmul2(u2h(x), half05))));
    return h2u(__hfma2(t, half05, half05));
}
static __device__ __forceinline__ void ffma2(ull& c, ull a, ull b) {
    asm("fma.rn.f32x2 %0, %1, %2, %0;" : "+l"(c) : "l"(a), "l"(b));
}
static __device__ __forceinline__ ull pack2f(float x, float y) {
    ull r;
    asm("mov.b64 %0, {%1, %2};" : "=l"(r)
        : "r"(__float_as_uint(x)), "r"(__float_as_uint(y)));
    return r;
}
static __device__ __forceinline__ float2 unpk2f(ull v) {
    unsigned int lo, hi;
    asm("mov.b64 {%0, %1}, %2;" : "=r"(lo), "=r"(hi) : "l"(v));
    return make_float2(__uint_as_float(lo), __uint_as_float(hi));
}

#define MMA6(accp, A, B0, B1, B2) \
    mma4((accp) + 0,  A, B0.x, B0.y); mma4((accp) + 4,  A, B0.z, B0.w); \
    mma4((accp) + 8,  A, B1.x, B1.y); mma4((accp) + 12, A, B1.z, B1.w); \
    mma4((accp) + 16, A, B2.x, B2.y); mma4((accp) + 20, A, B2.z, B2.w);

// one 6-kt chunk, single fp16 pass; warp covers 2 mtiles x 6 ntiles
static __device__ __forceinline__ void chunk_mma(uint32_t abA, uint32_t bb,
                                                 uint32_t aoffb, uint32_t boffb, float* acc) {
#pragma unroll
    for (int kt = 0; kt < 6; ++kt) {
        uint32_t aa = abA + kt * 4096 + aoffb;
        uint4 a0 = lds128(aa), a1 = lds128(aa + 512);
        uint32_t bo = kt * 3584 + boffb;
        uint4 B0 = lds128(bb + bo), B1 = lds128(bb + bo + 16), B2 = lds128(bb + bo + 32);
        MMA6(acc,      a0, B0, B1, B2);
        MMA6(acc + 24, a1, B0, B1, B2);
    }
}

// ===== prep: pack fp16 weights (bias folded) into frag-major images =====
__global__ void prep_kernel(const float* __restrict__ eW, const float* __restrict__ eb1,
                            const float* __restrict__ eb2, const float* __restrict__ dW,
                            const float* __restrict__ db1, const float* __restrict__ db2) {
    int idx = blockIdx.x * 256 + threadIdx.x;
    const int goff[3] = {0, 180, 270};  // i, g, o (f gate skipped: c0 = 0)
    if (idx < 3 * 96 * 96) {
        int gate = idx / (96 * 96), rem = idx % (96 * 96);
        int n = rem / 96, kp = rem % 96;
        int k = 2 * kp;
        float v0 = 0.f, v1 = 0.f;
        if (n < NH) {
            if (k < NF) { v0 = eW[(goff[gate] + n) * NF + k]; v1 = eW[(goff[gate] + n) * NF + k + 1]; }
            else if (k == NF) v0 = eb1[goff[gate] + n] + eb2[goff[gate] + n];
        }
        int pos = ((kp >> 3) * 32 + ((n & 7) << 2) + (kp & 3)) * 28 + (n >> 3) * 2 + ((kp >> 2) & 1);
        g_eBF[gate * EB_G + pos] = packh2(v0, v1);
        return;
    }
    int j = idx - 3 * 96 * 96;
    if (j < 3 * 96 * 48) {
        int gate = j / (96 * 48), rem = j % (96 * 48);
        int n = rem / 48, kp = rem % 48;
        int k = 2 * kp;
        float v0 = 0.f, v1 = 0.f;
        if (n < NH) {
            if (k < NH) { v0 = dW[(goff[gate] + n) * NH + k]; v1 = dW[(goff[gate] + n) * NH + k + 1]; }
            else if (k == NH) v0 = db1[goff[gate] + n] + db2[goff[gate] + n];
        }
        int pos = ((kp >> 3) * 32 + ((n & 7) << 2) + (kp & 3)) * 28 + (n >> 3) * 2 + ((kp >> 2) & 1);
        g_dBF[gate * DB_G + pos] = packh2(v0, v1);
    }
}

// ===== fused LSTM: single-pass fp16 mma.sync, 2 CTAs/SM, f16x2 epilogues =====
__global__ void __launch_bounds__(256, 2)
lstm_mma_kernel(const float* __restrict__ x) {
    extern __shared__ char smem[];
    const uint32_t sb = smem_u32(smem);
    const int tid = threadIdx.x, wid = tid >> 5, lane = tid & 31;
    const int b = blockIdx.x >> 1, th = blockIdx.x & 1;
    const int t0 = th * 120;
    const int tig = lane & 3, q = lane >> 2;
    const int mg = wid >> 1, ng = wid & 1;
    const uint32_t aoffb = (uint32_t)(mg * 2 * 512 + lane * 16);
    const uint32_t boffb = (uint32_t)(lane * 112 + ng * 48);

    // zero enc A region (49152B)
    for (int i = tid; i < 3072; i += 256) sts128z(sb + (uint32_t)(i * 16));

    // stage x coalesced, scatter fp16 into enc A frags (two 90-feature phases)
    float* Sx = reinterpret_cast<float*>(smem + OFF_B);
    for (int ph = 0; ph < 2; ++ph) {
        __syncthreads();
        const float* xb = x + ((size_t)b * NF + ph * 90) * NT + t0;
        for (int i = tid; i < 2700; i += 256) {
            int f = i / 30, c = i % 30;
            const float4 v = *reinterpret_cast<const float4*>(xb + f * NT + c * 4);
            *reinterpret_cast<float4*>(Sx + f * 120 + c * 4) = v;
        }
        __syncthreads();
        for (int i = tid; i < 5400; i += 256) {
            int r = i / 45, kpl = i % 45;
            int kp = ph * 45 + kpl, fp = 2 * kpl;
            uint32_t hv = packh2(Sx[fp * 120 + r], Sx[(fp + 1) * 120 + r]);
            int rr = r & 15, mt = r >> 4;
            int lne = ((rr & 7) << 2) | (kp & 3);
            int reg = (((kp >> 2) & 1) << 1) | (rr >> 3);
            uint32_t woff = (uint32_t)(((((kp >> 3) * 8 + mt) * 32 + lne) * 4 + reg) * 4);
            sts32(sb + OFF_AH + woff, hv);
        }
    }
    // enc bias column (k=180 -> kt 11, lane k-part 2, regs 0&1): fp16 1.0
    if (tid < 64) {
        int mt = tid >> 3, qq = tid & 7;
        uint32_t addr = sb + OFF_AH + (uint32_t)((((11 * 8 + mt) * 32 + ((qq << 2) | 2)) * 4) * 4);
        sts64(addr, 0x00003C00u, 0x00003C00u);
    }
    __syncthreads();  // Sx readers done before prefetch overwrites B region

    auto src = [&](int c) -> const uint4* {
        if (c < 6) return reinterpret_cast<const uint4*>(g_eBF + (c >> 1) * EB_G + (c & 1) * 5376);
        return reinterpret_cast<const uint4*>(g_dBF + (c - 6) * DB_G);
    };
    auto prefetch = [&](int c) {
        uint32_t d = sb + OFF_B + (uint32_t)((c & 1) * CHUNK_B);
        const uint4* s = src(c);
        for (int i = tid; i < 1344; i += 256) cp16(d + (uint32_t)(i * 16), s + i);
        CP_COMMIT();
    };

    prefetch(0);
    prefetch(1);

    float acc[48];
    uint32_t svp[24];   // packed fp16 gate-state carry (sig(i), then c)

#pragma unroll
    for (int c = 0; c < 9; ++c) {
        if (c < 8) { CP_WAIT1(); } else { CP_WAIT0(); }
        __syncthreads();  // chunk c visible; prior epilogue smem writes visible

        if (c == 0 || c == 2 || c == 4 || c >= 6) {
#pragma unroll
            for (int i = 0; i < 48; ++i) acc[i] = 0.f;
        }
        uint32_t abA = (c < 6) ? (sb + OFF_AH + (uint32_t)((c & 1) * 24576))
                               : (sb + OFF_ADH);
        uint32_t bb = sb + OFF_B + (uint32_t)((c & 1) * CHUNK_B);
        chunk_mma(abA, bb, aoffb, boffb, acc);

        if (c == 5) __syncthreads();  // all enc-A readers done before dec-A scatter

        // epilogues (packed f16x2 activations)
        if (c == 1 || c == 6) {
#pragma unroll
            for (int g = 0; g < 12; ++g) {
                svp[2 * g]     = h2sig(packh2(acc[4 * g],     acc[4 * g + 1]));
                svp[2 * g + 1] = h2sig(packh2(acc[4 * g + 2], acc[4 * g + 3]));
            }
        } else if (c == 3 || c == 7) {
#pragma unroll
            for (int g = 0; g < 12; ++g) {
                svp[2 * g]     = h2u(__hmul2(u2h(svp[2 * g]),
                                   u2h(h2tanh(packh2(acc[4 * g], acc[4 * g + 1])))));
                svp[2 * g + 1] = h2u(__hmul2(u2h(svp[2 * g + 1]),
                                   u2h(h2tanh(packh2(acc[4 * g + 2], acc[4 * g + 3])))));
            }
        } else if (c == 5) {
            // h1 = sig(sig(o)*tanh(c)) -> scatter fp16 into dec A frags (own-lane writes)
#pragma unroll
            for (int mi = 0; mi < 2; ++mi) {
#pragma unroll
                for (int ni = 0; ni < 6; ++ni) {
                    int g = mi * 6 + ni;
                    const float* a = acc + g * 4;
                    int nt = ng * 6 + ni;
                    uint32_t hv1, hv2;
                    if (nt == 11 && tig >= 1) {
                        hv1 = hv2 = (tig == 1) ? 0x00003C00u : 0u;  // dec bias col j=90
                    } else {
                        hv1 = h2sig(h2u(__hmul2(u2h(h2sig(packh2(a[0], a[1]))),
                                                u2h(h2tanh(svp[2 * g])))));
                        hv2 = h2sig(h2u(__hmul2(u2h(h2sig(packh2(a[2], a[3]))),
                                                u2h(h2tanh(svp[2 * g + 1])))));
                    }
                    int jp = nt * 4 + tig;
                    int ktd = jp >> 3, regb = ((jp >> 2) & 1) << 1;
                    int mtd = mg * 2 + mi;
                    uint32_t w = sb + OFF_ADH +
                        (uint32_t)(((((ktd * 8 + mtd) * 32 + lane) * 4) + regb) * 4);
                    sts64(w, hv1, hv2);
                }
            }
        } else if (c == 8) {
            // h2 = sig(o)*tanh(c) -> g_h2h (fp16)
            __half* hb = g_h2h + (size_t)b * (NT * NH) + (size_t)t0 * NH;
#pragma unroll
            for (int mi = 0; mi < 2; ++mi) {
#pragma unroll
                for (int ni = 0; ni < 6; ++ni) {
                    int nt = ng * 6 + ni;
                    if (nt == 11 && tig >= 1) continue;
                    int g = mi * 6 + ni;
                    const float* a = acc + g * 4;
                    int j0 = nt * 8 + 2 * tig;
                    int r1 = (mg * 2 + mi) * 16 + q, r2 = r1 + 8;
                    uint32_t p1 = h2u(__hmul2(u2h(h2sig(packh2(a[0], a[1]))),
                                              u2h(h2tanh(svp[2 * g]))));
                    *reinterpret_cast<uint32_t*>(hb + r1 * NH + j0) = p1;
                    if (r2 < 120) {
                        uint32_t p2 = h2u(__hmul2(u2h(h2sig(packh2(a[2], a[3]))),
                                                  u2h(h2tanh(svp[2 * g + 1]))));
                        *reinterpret_cast<uint32_t*>(hb + r2 * NH + j0) = p2;
                    }
                }
            }
        }

        __syncthreads();  // buf[c&1] readers done; epilogue smem writes published
        if (c + 2 < 9) prefetch(c + 2);
    }
}

// ===== output GEMM: 512 threads, 128 batches/block (quartered W traffic) =====
__global__ void __launch_bounds__(512, 1)
out_gemm_kernel(const float* __restrict__ W) {
    extern __shared__ float sm[];
    float* Hs = sm;                          // [240][131]
    float* Wt = sm + 240 * OG_HS_STRIDE;     // [240][44]
    const int b0 = blockIdx.y * 128;
    const int k0 = blockIdx.x * (21600 / KS);
    const int tid = threadIdx.x, wi = tid >> 5, lane = tid & 31;
    const int bbl = (wi & 3) * 32 + lane;    // local batch column 0..127
    const int ksl = wi >> 2;                 // k-slice 0..3 (60 k each)

    ull acc[20];
#pragma unroll
    for (int n = 0; n < 20; ++n) acc[n] = 0ull;

    for (int tile = 0; tile < (21600 / KS) / 240; ++tile) {
        const int kt = k0 + tile * 240;
        __syncthreads();
        for (int idx = tid; idx < 128 * 120; idx += 512) {
            int bb = idx / 120, k2 = idx - bb * 120;
            __half2 h = *reinterpret_cast<const __half2*>(
                g_h2h + (size_t)(b0 + bb) * 21600 + kt + 2 * k2);
            float2 f = __half22float2(h);
            Hs[(2 * k2) * OG_HS_STRIDE + bb] = f.x;
            Hs[(2 * k2 + 1) * OG_HS_STRIDE + bb] = f.y;
        }
        for (int idx = tid; idx < 40 * 240; idx += 512) {
            int n = idx / 240, k = idx - n * 240;
            Wt[k * 44 + n] = W[(size_t)n * 21600 + kt + k];
        }
        __syncthreads();
#pragma unroll 2
        for (int kk = 0; kk < 60; ++kk) {
            int k = ksl * 60 + kk;
            float h = Hs[k * OG_HS_STRIDE + bbl];
            ull hh = pack2f(h, h);
            const ull* wp = reinterpret_cast<const ull*>(Wt + k * 44);
#pragma unroll
            for (int n2 = 0; n2 < 20; ++n2) ffma2(acc[n2], hh, wp[n2]);
        }
    }
    __syncthreads();
    float* Rs = sm;   // [4 ksl][128 bb][40] = 20480 floats (fits)
#pragma unroll
    for (int n2 = 0; n2 < 20; ++n2) {
        float2 v = unpk2f(acc[n2]);
        Rs[(ksl * 128 + bbl) * 40 + 2 * n2] = v.x;
        Rs[(ksl * 128 + bbl) * 40 + 2 * n2 + 1] = v.y;
    }
    __syncthreads();
    for (int idx = tid; idx < 128 * 40; idx += 512) {
        int bb = idx / 40, n = idx - bb * 40;
        float s = 0.f;
#pragma unroll
        for (int w = 0; w < 4; ++w) s += Rs[(w * 128 + bb) * 40 + n];
        g_part[blockIdx.x * (NB * 40) + (b0 + bb) * 40 + n] = s;
    }
}

// 4 batches per 160-thread block
__global__ void softmax_kernel(const float* __restrict__ ob, float* __restrict__ out) {
    __shared__ float L[160];
    __shared__ float E[160];
    const int tl = threadIdx.x;
    const int bl = tl / 40, n = tl - bl * 40;
    const int b = blockIdx.x * 4 + bl;
    float s = 0.f;
#pragma unroll
    for (int ks = 0; ks < KS; ++ks) s += g_part[ks * (NB * 40) + b * 40 + n];
    s += ob[n];
    L[tl] = s;
    __syncthreads();
    const int g0 = bl * 40 + (n / 10) * 10;
    float mx = -1e30f;
#pragma unroll
    for (int i = 0; i < 10; ++i) mx = fmaxf(mx, L[g0 + i]);
    float e = __expf(s - mx);
    E[tl] = e;
    __syncthreads();
    float sum = 0.f;
#pragma unroll
    for (int i = 0; i < 10; ++i) sum += E[g0 + i];
    out[b * 40 + n] = __fdividef(e, sum);
}

extern "C" void kernel_launch(void* const* d_in, const int* in_sizes, int n_in,
                              void* d_out, int out_size) {
    const float* x   = (const float*)d_in[0];
    const float* eW  = (const float*)d_in[1];
    const float* eb1 = (const float*)d_in[2];
    const float* eb2 = (const float*)d_in[3];
    const float* dW  = (const float*)d_in[4];
    const float* db1 = (const float*)d_in[5];
    const float* db2 = (const float*)d_in[6];
    const float* oW  = (const float*)d_in[7];
    const float* ob  = (const float*)d_in[8];
    float* out = (float*)d_out;

    cudaFuncSetAttribute(lstm_mma_kernel,
                         cudaFuncAttributeMaxDynamicSharedMemorySize, SMEM_LSTM);
    cudaFuncSetAttribute(out_gemm_kernel,
                         cudaFuncAttributeMaxDynamicSharedMemorySize,
                         OG_SMEM_FLOATS * 4);

    prep_kernel<<<162, 256>>>(eW, eb1, eb2, dW, db1, db2);
    lstm_mma_kernel<<<2048, 256, SMEM_LSTM>>>(x);
    out_gemm_kernel<<<dim3(KS, 8), 512, OG_SMEM_FLOATS * 4>>>(oW);
    softmax_kernel<<<256, 160>>>(ob, out);
}